// round 8
// baseline (speedup 1.0000x reference)
#include <cuda_runtime.h>
#include <cuda_bf16.h>
#include <cmath>

#define NN 50000
#define EE 800000
#define EF 850000          // EE + NN self loops
#define ND (NN*64)

// ---------------- scratch (device globals; no allocation) ----------------
__device__ int    g_deg[NN];          // zero at load; re-zeroed by k_fill each call
__device__ int    g_rowptr[NN+1];
__device__ int    g_cursor[NN];
__device__ int    g_csr_src[EF];
__device__ int    g_csr_tsrc[EF];
__device__ float  g_el[ND];
__device__ float  g_er[ND];
__device__ float  g_agg[2*ND];        // agg0 | agg1 (per-etype h sums)
__device__ float2 g_cnt[NN];          // (#type0, #type1) incoming edges
// per-layer prepped weight image (bf16 hi/lo, 144B row stride, smem-ready):
// [0:18432)        GAT [Wsrc;Wdst] hi (128 rows)   [18432:36864)  lo
// [36864:64512)    M0 = Wih@W0 hi (192 rows)       [64512:92160)  lo
// [92160:119808)   M1 = Wih@W1 hi                  [119808:147456) lo
// [147456:175104)  Whh hi                          [175104:202752) lo
#define IMG_U4 12672                  // 202752 B per layer
__device__ uint4  g_wimg[2][IMG_U4];
__device__ float  g_uvec[2][384];     // u_t[j] = (Wih@b_t)[j]; t0:[0,192) t1:[192,384)

// ---------------- bf16 split + mma helpers ----------------
__device__ __forceinline__ unsigned smem_u32(const void* p){
    unsigned a; asm("{ .reg .u64 t; cvta.to.shared.u64 t, %1; cvt.u32.u64 %0, t; }" : "=r"(a) : "l"(p));
    return a;
}
__device__ __forceinline__ void bsplit(float x, unsigned short& h, unsigned short& l){
    __nv_bfloat16 bh = __float2bfloat16(x);
    h = __bfloat16_as_ushort(bh);
    l = __bfloat16_as_ushort(__float2bfloat16(x - __bfloat162float(bh)));
}
__device__ __forceinline__ void split2(float a, float b, unsigned& h, unsigned& l){
    unsigned short ha, la, hb, lb;
    bsplit(a, ha, la); bsplit(b, hb, lb);
    h = (unsigned)ha | ((unsigned)hb << 16);
    l = (unsigned)la | ((unsigned)lb << 16);
}
__device__ __forceinline__ void ldsm4(unsigned* r, unsigned addr){
    asm volatile("ldmatrix.sync.aligned.m8n8.x4.shared.b16 {%0,%1,%2,%3}, [%4];"
        : "=r"(r[0]), "=r"(r[1]), "=r"(r[2]), "=r"(r[3]) : "r"(addr));
}
__device__ __forceinline__ void ldsm2(unsigned* r, unsigned addr){
    asm volatile("ldmatrix.sync.aligned.m8n8.x2.shared.b16 {%0,%1}, [%2];"
        : "=r"(r[0]), "=r"(r[1]) : "r"(addr));
}
__device__ __forceinline__ void mma16816(float* c, const unsigned* a, const unsigned* b){
    asm volatile("mma.sync.aligned.m16n8k16.row.col.f32.bf16.bf16.f32 "
        "{%0,%1,%2,%3}, {%4,%5,%6,%7}, {%8,%9}, {%0,%1,%2,%3};"
        : "+f"(c[0]), "+f"(c[1]), "+f"(c[2]), "+f"(c[3])
        : "r"(a[0]), "r"(a[1]), "r"(a[2]), "r"(a[3]), "r"(b[0]), "r"(b[1]));
}

// stage 16 fp32 -> bf16 hi/lo smem (144B row stride)
__device__ __forceinline__ void stage_row16(const float* __restrict__ src, int grow, int n,
                                            int row, int q, char* bh, char* bl)
{
    float4 v0, v1, v2, v3;
    if (grow < n) {
        const float4* s = (const float4*)(src + grow*64 + q);
        v0 = s[0]; v1 = s[1]; v2 = s[2]; v3 = s[3];
    } else {
        v0 = v1 = v2 = v3 = make_float4(0.f, 0.f, 0.f, 0.f);
    }
    unsigned* dh = (unsigned*)(bh + row*144 + q*2);
    unsigned* dl = (unsigned*)(bl + row*144 + q*2);
    split2(v0.x, v0.y, dh[0], dl[0]); split2(v0.z, v0.w, dh[1], dl[1]);
    split2(v1.x, v1.y, dh[2], dl[2]); split2(v1.z, v1.w, dh[3], dl[3]);
    split2(v2.x, v2.y, dh[4], dl[4]); split2(v2.z, v2.w, dh[5], dl[5]);
    split2(v3.x, v3.y, dh[6], dl[6]); split2(v3.z, v3.w, dh[7], dl[7]);
}

// ---------------- CSR build ----------------
__global__ void k_deg(const int* __restrict__ dst) {
    int e = blockIdx.x*blockDim.x + threadIdx.x;
    if (e >= EF) return;
    int d = (e < EE) ? dst[e] : (e - EE);
    atomicAdd(&g_deg[d], 1);
}
__global__ void k_scan() {
    __shared__ int part[1024];
    int t = threadIdx.x;
    const int CH = (NN + 1023) / 1024;
    int base = t * CH;
    int s = 0;
    for (int i = 0; i < CH; i++) { int idx = base + i; if (idx < NN) s += g_deg[idx]; }
    part[t] = s; __syncthreads();
    for (int off = 1; off < 1024; off <<= 1) {
        int v = (t >= off) ? part[t - off] : 0;
        __syncthreads();
        part[t] += v;
        __syncthreads();
    }
    int run = (t == 0) ? 0 : part[t-1];
    for (int i = 0; i < CH; i++) {
        int idx = base + i;
        if (idx < NN) { g_rowptr[idx] = run; g_cursor[idx] = run; run += g_deg[idx]; }
    }
    if (t == 1023) g_rowptr[NN] = run;
}
__global__ void k_fill(const int* __restrict__ src, const int* __restrict__ dst,
                       const int* __restrict__ ety) {
    int e = blockIdx.x*blockDim.x + threadIdx.x;
    if (e >= EF) return;
    int s = (e < EE) ? src[e] : (e - EE);
    int d = (e < EE) ? dst[e] : (e - EE);
    int t = ety[e];
    int pos = atomicAdd(&g_cursor[d], 1);
    g_csr_src[pos]  = s;
    g_csr_tsrc[pos] = t*NN + s;
    if (e < NN) g_deg[e] = 0;   // restore zero invariant for next replay
}

// ---------------- combined weight prep: bf16 images + GGC fold (both layers) ----------------
__global__ void k_prep_all(
    const float* __restrict__ Wsrc0, const float* __restrict__ Wdst0,
    const float* __restrict__ gW0,   const float* __restrict__ gb0,
    const float* __restrict__ Wih0,  const float* __restrict__ Whh0,
    const float* __restrict__ Wsrc1, const float* __restrict__ Wdst1,
    const float* __restrict__ gW1,   const float* __restrict__ gb1,
    const float* __restrict__ Wih1,  const float* __restrict__ Whh1,
    uint4* __restrict__ img, float* __restrict__ uvec)
{
    int i = blockIdx.x*blockDim.x + threadIdx.x;
    if (i < 16384) {                              // GAT images (2 layers x 128 x 64)
        int l = i >> 13, r = (i >> 6) & 127, d = i & 63;
        const float* Ws = l ? Wsrc1 : Wsrc0;
        const float* Wd = l ? Wdst1 : Wdst0;
        float v = (r < 64) ? Ws[r*64 + d] : Wd[(r-64)*64 + d];
        unsigned short h, lo; bsplit(v, h, lo);
        char* base = (char*)img + l*202752;
        *(unsigned short*)(base + r*144 + d*2) = h;
        *(unsigned short*)(base + 18432 + r*144 + d*2) = lo;
    } else if (i < 65536) {                       // M_t = Wih@W_t (2 x 2 x 192 x 64)
        int i2 = i - 16384;
        int l = i2 / 24576, r2 = i2 % 24576;
        int t = r2 / 12288, j = (r2 >> 6) % 192, d = r2 & 63;
        const float* Wih = l ? Wih1 : Wih0;
        const float* gW  = l ? gW1  : gW0;
        float s = 0.f;
        #pragma unroll 8
        for (int o = 0; o < 64; o++) s += Wih[j*64 + o] * gW[t*4096 + o*64 + d];
        unsigned short h, lo; bsplit(s, h, lo);
        char* base = (char*)img + l*202752 + 36864 + t*55296;
        *(unsigned short*)(base + j*144 + d*2) = h;
        *(unsigned short*)(base + 27648 + j*144 + d*2) = lo;
    } else if (i < 90112) {                       // Whh images (2 x 192 x 64)
        int i2 = i - 65536;
        int l = i2 / 12288, r2 = i2 % 12288;
        int j = r2 >> 6, d = r2 & 63;
        const float* Whh = l ? Whh1 : Whh0;
        float v = Whh[j*64 + d];
        unsigned short h, lo; bsplit(v, h, lo);
        char* base = (char*)img + l*202752 + 147456;
        *(unsigned short*)(base + j*144 + d*2) = h;
        *(unsigned short*)(base + 27648 + j*144 + d*2) = lo;
    } else if (i < 90880) {                       // u_t = Wih@b_t (2 x 2 x 192)
        int i2 = i - 90112;
        int l = i2 / 384, r2 = i2 % 384;
        int t = r2 / 192, j = r2 % 192;
        const float* Wih = l ? Wih1 : Wih0;
        const float* gb  = l ? gb1  : gb0;
        float u = 0.f;
        #pragma unroll 8
        for (int o = 0; o < 64; o++) u += Wih[j*64 + o] * gb[t*64 + o];
        uvec[l*384 + t*192 + j] = u;
    }
}

// ---------------- MMA dual GEMM (GAT projections) ----------------
#define G_OAh 0
#define G_OAl 9216
#define G_OW  18432           // W hi | W lo contiguous (36864B)
#define G_SMEM 55296

__global__ __launch_bounds__(256, 1) void gemm_mma(
    const float* __restrict__ A, const uint4* __restrict__ wimg,
    const float* __restrict__ b0, const float* __restrict__ b1,
    float* __restrict__ C0, float* __restrict__ C1, int n)
{
    extern __shared__ char sm[];
    unsigned sb = smem_u32(sm);
    int tid = threadIdx.x, wid = tid >> 5, lane = tid & 31;
    int m0 = blockIdx.x * 64;

    stage_row16(A, m0 + (tid >> 2), n, tid >> 2, (tid & 3) << 4, sm + G_OAh, sm + G_OAl);
    for (int i = tid; i < 2304; i += 256) ((uint4*)(sm + G_OW))[i] = wimg[i];
    __syncthreads();

    int mt = wid & 3, hf = wid >> 2;
    int rowit = ((lane >> 3) & 1)*8 + (lane & 7);
    unsigned aBh = sb + G_OAh + (mt*16 + rowit)*144 + ((lane >> 4) << 4);
    unsigned aBl = sb + G_OAl + (mt*16 + rowit)*144 + ((lane >> 4) << 4);
    int bl_ = lane & 15;
    unsigned bRow = (unsigned)((hf*64 + (bl_ & 7))*144 + ((bl_ >> 3) << 4));

    float c[8][4];
    #pragma unroll
    for (int t = 0; t < 8; t++) { c[t][0]=0.f; c[t][1]=0.f; c[t][2]=0.f; c[t][3]=0.f; }

    #pragma unroll
    for (int kk = 0; kk < 4; kk++) {
        unsigned ah[4], al[4];
        ldsm4(ah, aBh + kk*32);
        ldsm4(al, aBl + kk*32);
        #pragma unroll
        for (int ct = 0; ct < 8; ct++) {
            unsigned off = bRow + ct*(8*144) + kk*32;
            unsigned wh[2], wl[2];
            ldsm2(wh, sb + G_OW + off);
            ldsm2(wl, sb + G_OW + 18432 + off);
            mma16816(c[ct], ah, wh);
            mma16816(c[ct], al, wh);
            mma16816(c[ct], ah, wl);
        }
    }

    int r0 = mt*16 + (lane >> 2);
    int cb = (lane & 3)*2;
    const float* bb = hf ? b1 : b0;
    float* C = hf ? C1 : C0;
    #pragma unroll
    for (int ct = 0; ct < 8; ct++) {
        int j = ct*8 + cb;
        float2 bv = *(const float2*)&bb[j];
        #pragma unroll
        for (int rh = 0; rh < 2; rh++) {
            int grow = m0 + r0 + rh*8;
            if (grow < n) {
                float2 o = make_float2(c[ct][rh*2] + bv.x, c[ct][rh*2+1] + bv.y);
                *(float2*)&C[grow*64 + j] = o;
            }
        }
    }
}

// ---------------- fused GATv2 edge-softmax + aggregation ----------------
__global__ void k_gat(const float* __restrict__ attn,
                      float* __restrict__ out0, float* __restrict__ out1)
{
    int gt = blockIdx.x*blockDim.x + threadIdx.x;
    int v = gt >> 5, lane = gt & 31;
    if (v >= NN) return;
    float2 erv = *reinterpret_cast<const float2*>(&g_er[v*64 + lane*2]);
    float a0 = __ldg(&attn[lane*2]), a1 = __ldg(&attn[lane*2 + 1]);
    int p0 = g_rowptr[v], p1 = g_rowptr[v+1];
    float m = __int_as_float(0xff800000);
    float den = 0.f, ac0 = 0.f, ac1 = 0.f;
    int p = p0;
    for (; p + 2 <= p1; p += 2) {
        int sA = __ldg(&g_csr_src[p]);
        int sB = __ldg(&g_csr_src[p+1]);
        float2 eA = *reinterpret_cast<const float2*>(&g_el[sA*64 + lane*2]);
        float2 eB = *reinterpret_cast<const float2*>(&g_el[sB*64 + lane*2]);
        float tA0 = eA.x + erv.x; tA0 = (tA0 > 0.f) ? tA0 : 0.2f*tA0;
        float tA1 = eA.y + erv.y; tA1 = (tA1 > 0.f) ? tA1 : 0.2f*tA1;
        float tB0 = eB.x + erv.x; tB0 = (tB0 > 0.f) ? tB0 : 0.2f*tB0;
        float tB1 = eB.y + erv.y; tB1 = (tB1 > 0.f) ? tB1 : 0.2f*tB1;
        float scA = tA0*a0 + tA1*a1;
        float scB = tB0*a0 + tB1*a1;
        #pragma unroll
        for (int off = 16; off > 0; off >>= 1) {
            scA += __shfl_xor_sync(0xffffffffu, scA, off);
            scB += __shfl_xor_sync(0xffffffffu, scB, off);
        }
        float nm = fmaxf(m, scA);
        float scale = __expf(m - nm);
        float w = __expf(scA - nm);
        den = den*scale + w;
        ac0 = ac0*scale + w*eA.x;
        ac1 = ac1*scale + w*eA.y;
        m = nm;
        nm = fmaxf(m, scB);
        scale = __expf(m - nm);
        w = __expf(scB - nm);
        den = den*scale + w;
        ac0 = ac0*scale + w*eB.x;
        ac1 = ac1*scale + w*eB.y;
        m = nm;
    }
    for (; p < p1; p++) {
        int s = __ldg(&g_csr_src[p]);
        float2 elv = *reinterpret_cast<const float2*>(&g_el[s*64 + lane*2]);
        float t0 = elv.x + erv.x; t0 = (t0 > 0.f) ? t0 : 0.2f*t0;
        float t1 = elv.y + erv.y; t1 = (t1 > 0.f) ? t1 : 0.2f*t1;
        float sc = t0*a0 + t1*a1;
        #pragma unroll
        for (int off = 16; off > 0; off >>= 1) sc += __shfl_xor_sync(0xffffffffu, sc, off);
        float nm = fmaxf(m, sc);
        float scale = __expf(m - nm);
        float w = __expf(sc - nm);
        den = den*scale + w;
        ac0 = ac0*scale + w*elv.x;
        ac1 = ac1*scale + w*elv.y;
        m = nm;
    }
    float inv = 1.f / den;
    float o0 = ac0*inv, o1 = ac1*inv;
    o0 = (o0 > 0.f) ? o0 : expm1f(o0);
    o1 = (o1 > 0.f) ? o1 : expm1f(o1);
    float2 r = make_float2(o0, o1);
    *reinterpret_cast<float2*>(&out0[v*64 + lane*2]) = r;
    *reinterpret_cast<float2*>(&out1[v*64 + lane*2]) = r;
}

// ---------------- per-etype gather of h (for folded GGC) ----------------
__global__ void k_agg2(const float* __restrict__ H) {
    int gt = blockIdx.x*blockDim.x + threadIdx.x;
    int v = gt >> 5, lane = gt & 31;
    if (v >= NN) return;
    int p0 = g_rowptr[v], p1 = g_rowptr[v+1];
    float a0x=0.f, a0y=0.f, a1x=0.f, a1y=0.f; int c1 = 0;
    int p = p0;
    for (; p + 2 <= p1; p += 2) {
        int tsA = __ldg(&g_csr_tsrc[p]);
        int tsB = __ldg(&g_csr_tsrc[p+1]);
        int tA = tsA >= NN, tB = tsB >= NN;
        int sA = tA ? tsA - NN : tsA;
        int sB = tB ? tsB - NN : tsB;
        float2 hA = *(const float2*)&H[sA*64 + lane*2];
        float2 hB = *(const float2*)&H[sB*64 + lane*2];
        if (tA) { a1x += hA.x; a1y += hA.y; c1++; } else { a0x += hA.x; a0y += hA.y; }
        if (tB) { a1x += hB.x; a1y += hB.y; c1++; } else { a0x += hB.x; a0y += hB.y; }
    }
    for (; p < p1; p++) {
        int ts = __ldg(&g_csr_tsrc[p]);
        int t = ts >= NN;
        int s = t ? ts - NN : ts;
        float2 h = *(const float2*)&H[s*64 + lane*2];
        if (t) { a1x += h.x; a1y += h.y; c1++; } else { a0x += h.x; a0y += h.y; }
    }
    *(float2*)&g_agg[v*64 + lane*2]      = make_float2(a0x, a0y);
    *(float2*)&g_agg[ND + v*64 + lane*2] = make_float2(a1x, a1y);
    if (lane == 0) g_cnt[v] = make_float2((float)(p1 - p0 - c1), (float)c1);
}

// ---------------- persistent MMA GRU (folded: gi = M0@agg0 + M1@agg1 + cnt.u) ----------------
#define R_OA0h 0
#define R_OA0l 9216
#define R_OA1h 18432
#define R_OA1l 27648
#define R_OHh  36864
#define R_OHl  46080
#define R_OW   55296          // M0 h/l, M1 h/l, Whh h/l (165888B)
#define R_SMEM 221184

__global__ __launch_bounds__(256, 1) void gru_mma(
    const float* __restrict__ H, const uint4* __restrict__ wimg,
    const float* __restrict__ uvec,
    const float* __restrict__ bih, const float* __restrict__ bhh,
    float* __restrict__ Hout, int n)
{
    extern __shared__ char sm[];
    unsigned sb = smem_u32(sm);
    int tid = threadIdx.x, wid = tid >> 5, lane = tid & 31;

    // stage prepped weights once (10368 uint4 = 165888B)
    for (int i = tid; i < 10368; i += 256) ((uint4*)(sm + R_OW))[i] = wimg[i];

    int mt = wid & 3, hf = wid >> 2;
    int rowit = ((lane >> 3) & 1)*8 + (lane & 7);
    unsigned aOff = (unsigned)((mt*16 + rowit)*144 + ((lane >> 4) << 4));
    int bl_ = lane & 15;
    unsigned bBase = (unsigned)(((bl_ & 7))*144 + ((bl_ >> 3) << 4));
    int r0 = mt*16 + (lane >> 2);
    int cb = (lane & 3)*2;
    const unsigned OM0H = R_OW,          OM0L = R_OW + 27648;
    const unsigned OM1H = R_OW + 55296,  OM1L = R_OW + 82944;
    const unsigned OWhH = R_OW + 110592, OWhL = R_OW + 138240;

    for (int m0 = blockIdx.x*64; m0 < n; m0 += gridDim.x*64) {
        __syncthreads();
        {
            int row = tid >> 2, q = (tid & 3) << 4;
            int grow = m0 + row;
            stage_row16(g_agg,      grow, n, row, q, sm + R_OA0h, sm + R_OA0l);
            stage_row16(g_agg + ND, grow, n, row, q, sm + R_OA1h, sm + R_OA1l);
            stage_row16(H,          grow, n, row, q, sm + R_OHh,  sm + R_OHl);
        }
        __syncthreads();

        float cgi[12][4], cgh[12][4];
        #pragma unroll
        for (int t = 0; t < 12; t++) {
            cgi[t][0]=0.f; cgi[t][1]=0.f; cgi[t][2]=0.f; cgi[t][3]=0.f;
            cgh[t][0]=0.f; cgh[t][1]=0.f; cgh[t][2]=0.f; cgh[t][3]=0.f;
        }

        #pragma unroll
        for (int kk = 0; kk < 4; kk++) {
            unsigned a0h[4], a0l[4], a1h[4], a1l[4], ahh[4], ahl[4];
            ldsm4(a0h, sb + R_OA0h + aOff + kk*32);
            ldsm4(a0l, sb + R_OA0l + aOff + kk*32);
            ldsm4(a1h, sb + R_OA1h + aOff + kk*32);
            ldsm4(a1l, sb + R_OA1l + aOff + kk*32);
            ldsm4(ahh, sb + R_OHh  + aOff + kk*32);
            ldsm4(ahl, sb + R_OHl  + aOff + kk*32);
            #pragma unroll
            for (int g = 0; g < 3; g++) {
                #pragma unroll
                for (int jt = 0; jt < 4; jt++) {
                    unsigned off = bBase + (unsigned)((g*64 + hf*32 + jt*8)*144) + kk*32;
                    unsigned wh[2], wl[2];
                    float* ci = cgi[g*4 + jt];
                    ldsm2(wh, sb + OM0H + off);
                    ldsm2(wl, sb + OM0L + off);
                    mma16816(ci, a0h, wh);
                    mma16816(ci, a0l, wh);
                    mma16816(ci, a0h, wl);
                    ldsm2(wh, sb + OM1H + off);
                    ldsm2(wl, sb + OM1L + off);
                    mma16816(ci, a1h, wh);
                    mma16816(ci, a1l, wh);
                    mma16816(ci, a1h, wl);
                    float* ch = cgh[g*4 + jt];
                    ldsm2(wh, sb + OWhH + off);
                    ldsm2(wl, sb + OWhL + off);
                    mma16816(ch, ahh, wh);
                    mma16816(ch, ahl, wh);
                    mma16816(ch, ahh, wl);
                }
            }
        }

        #pragma unroll
        for (int jt = 0; jt < 4; jt++) {
            int j = hf*32 + jt*8 + cb;
            float2 bir = *(const float2*)&bih[j];
            float2 biz = *(const float2*)&bih[64 + j];
            float2 bic = *(const float2*)&bih[128 + j];
            float2 bhr = *(const float2*)&bhh[j];
            float2 bhz = *(const float2*)&bhh[64 + j];
            float2 bhc = *(const float2*)&bhh[128 + j];
            float2 u0r = *(const float2*)&uvec[j];
            float2 u0z = *(const float2*)&uvec[64 + j];
            float2 u0c = *(const float2*)&uvec[128 + j];
            float2 u1r = *(const float2*)&uvec[192 + j];
            float2 u1z = *(const float2*)&uvec[256 + j];
            float2 u1c = *(const float2*)&uvec[320 + j];
            #pragma unroll
            for (int rh = 0; rh < 2; rh++) {
                int grow = m0 + r0 + rh*8;
                if (grow < n) {
                    float2 cnt = g_cnt[grow];
                    float2 hp = *(const float2*)&H[grow*64 + j];
                    float o[2];
                    #pragma unroll
                    for (int e = 0; e < 2; e++) {
                        int idx = rh*2 + e;
                        float ir = cgi[jt][idx]   + cnt.x*(e?u0r.y:u0r.x) + cnt.y*(e?u1r.y:u1r.x) + (e?bir.y:bir.x);
                        float iz = cgi[4+jt][idx] + cnt.x*(e?u0z.y:u0z.x) + cnt.y*(e?u1z.y:u1z.x) + (e?biz.y:biz.x);
                        float ic = cgi[8+jt][idx] + cnt.x*(e?u0c.y:u0c.x) + cnt.y*(e?u1c.y:u1c.x) + (e?bic.y:bic.x);
                        float hr = cgh[jt][idx]   + (e?bhr.y:bhr.x);
                        float hz = cgh[4+jt][idx] + (e?bhz.y:bhz.x);
                        float hc = cgh[8+jt][idx] + (e?bhc.y:bhc.x);
                        float r = 1.f / (1.f + __expf(-(ir + hr)));
                        float z = 1.f / (1.f + __expf(-(iz + hz)));
                        float cn = tanhf(ic + r*hc);
                        float hprev = e ? hp.y : hp.x;
                        o[e] = (1.f - z)*cn + z*hprev;
                    }
                    *(float2*)&Hout[grow*64 + j] = make_float2(o[0], o[1]);
                }
            }
        }
    }
}

// ---------------- host pipeline ----------------
extern "C" void kernel_launch(void* const* d_in, const int* in_sizes, int n_in,
                              void* d_out, int out_size)
{
    const float* x   = (const float*)d_in[0];
    const int*   src = (const int*)d_in[1];
    const int*   dst = (const int*)d_in[2];
    const int*   ety = (const int*)d_in[3];
    float* out = (float*)d_out;

    cudaFuncSetAttribute(gemm_mma, cudaFuncAttributeMaxDynamicSharedMemorySize, G_SMEM);
    cudaFuncSetAttribute(gru_mma,  cudaFuncAttributeMaxDynamicSharedMemorySize, R_SMEM);

    float *p_el, *p_er, *p_uv;
    cudaGetSymbolAddress((void**)&p_el, g_el);
    cudaGetSymbolAddress((void**)&p_er, g_er);
    cudaGetSymbolAddress((void**)&p_uv, g_uvec);
    uint4* p_wimg;
    cudaGetSymbolAddress((void**)&p_wimg, g_wimg);

    // CSR build
    k_deg <<<(EF + 255)/256, 256>>>(dst);
    k_scan<<<1, 1024>>>();
    k_fill<<<(EF + 255)/256, 256>>>(src, dst, ety);

    // combined weight prep (both layers, one launch)
    k_prep_all<<<356, 256>>>(
        (const float*)d_in[4],  (const float*)d_in[6],  (const float*)d_in[9],
        (const float*)d_in[10], (const float*)d_in[11], (const float*)d_in[13],
        (const float*)d_in[15], (const float*)d_in[17], (const float*)d_in[20],
        (const float*)d_in[21], (const float*)d_in[22], (const float*)d_in[24],
        p_wimg, p_uv);

    const int gblocks   = (NN + 63) / 64;       // 782
    const int edgBlocks = (NN*32 + 255) / 256;

    for (int l = 0; l < 2; l++) {
        const float* bsrc = (const float*)d_in[4 + l*11 + 1];
        const float* bdst = (const float*)d_in[4 + l*11 + 3];
        const float* attn = (const float*)d_in[4 + l*11 + 4];
        const float* bih  = (const float*)d_in[4 + l*11 + 8];
        const float* bhh  = (const float*)d_in[4 + l*11 + 10];

        const float* xin = (l == 0) ? x : (out + 1*ND);
        float* gatOut = out + (2*l)*ND;
        float* hbuf   = out + (2*l + 1)*ND;
        const uint4* wimg = p_wimg + l*IMG_U4;

        gemm_mma<<<gblocks, 256, G_SMEM>>>(xin, wimg, bsrc, bdst, p_el, p_er, NN);
        k_gat<<<edgBlocks, 256>>>(attn, gatOut, hbuf);

        for (int step = 0; step < 2; step++) {
            k_agg2<<<edgBlocks, 256>>>(hbuf);
            gru_mma<<<148, 256, R_SMEM>>>(hbuf, wimg + 2304, p_uv + l*384, bih, bhh, hbuf, NN);
        }
    }
}